// round 12
// baseline (speedup 1.0000x reference)
#include <cuda_runtime.h>
#include <cuda_fp16.h>
#include <math.h>
#include <stdint.h>

// ---------------------------------------------------------------------------
// Problem constants
// ---------------------------------------------------------------------------
#define BATCH   16
#define LT      512
#define LI      576
#define TEXTD   768
#define IMGD    1024
#define HID     2048
#define HEADS   8
#define HDIM    256
#define FFD     128

#define MQ (BATCH*LT)   // 8192
#define MK (BATCH*LI)   // 9216

// ---------------------------------------------------------------------------
// Device scratch (pure fp16 pipeline)
// ---------------------------------------------------------------------------
__device__ float g_O[(size_t)MQ * TEXTD];

__device__ __half g_th[(size_t)MQ * TEXTD];
__device__ __half g_ih[(size_t)MK * IMGD];
__device__ __half g_qh[(size_t)MQ * HID];
__device__ __half g_kh[(size_t)MK * HID];
__device__ __half g_vh[(size_t)MK * HID];
__device__ __half g_xh[(size_t)MQ * HID];
__device__ __half g_wqh[(size_t)HID * TEXTD];
__device__ __half g_wkh[(size_t)HID * IMGD];
__device__ __half g_wvh[(size_t)HID * IMGD];
__device__ __half g_wrh[(size_t)TEXTD * HID];

// ---------------------------------------------------------------------------
// PTX helpers
// ---------------------------------------------------------------------------
__device__ __forceinline__ uint32_t smem_u32(const void* p) {
    uint32_t a;
    asm("{ .reg .u64 t; cvta.to.shared.u64 t, %1; cvt.u32.u64 %0, t; }"
        : "=r"(a) : "l"(p));
    return a;
}

__device__ __forceinline__ void ldm_x4(uint32_t* r, uint32_t addr) {
    asm volatile("ldmatrix.sync.aligned.m8n8.x4.shared.b16 {%0,%1,%2,%3}, [%4];"
                 : "=r"(r[0]), "=r"(r[1]), "=r"(r[2]), "=r"(r[3]) : "r"(addr));
}

__device__ __forceinline__ void ldm_x4t(uint32_t* r, uint32_t addr) {
    asm volatile("ldmatrix.sync.aligned.m8n8.x4.trans.shared.b16 {%0,%1,%2,%3}, [%4];"
                 : "=r"(r[0]), "=r"(r[1]), "=r"(r[2]), "=r"(r[3]) : "r"(addr));
}

__device__ __forceinline__ void mma16816(float* d, const uint32_t* a,
                                         const uint32_t* b) {
    asm volatile(
        "mma.sync.aligned.m16n8k16.row.col.f32.f16.f16.f32 "
        "{%0,%1,%2,%3}, {%4,%5,%6,%7}, {%8,%9}, {%0,%1,%2,%3};"
        : "+f"(d[0]), "+f"(d[1]), "+f"(d[2]), "+f"(d[3])
        : "r"(a[0]), "r"(a[1]), "r"(a[2]), "r"(a[3]), "r"(b[0]), "r"(b[1]));
}

#define CP_ASYNC16(smem, gptr) \
    asm volatile("cp.async.cg.shared.global [%0], [%1], 16;" \
        :: "r"(smem), "l"(gptr) : "memory")
#define CP_COMMIT() asm volatile("cp.async.commit_group;" ::: "memory")
#define CP_WAIT(n)  asm volatile("cp.async.wait_group %0;" :: "n"(n) : "memory")

// ---------------------------------------------------------------------------
// fp32 -> fp16 convert (vectorized by 4)
// ---------------------------------------------------------------------------
__global__ __launch_bounds__(256) void cvt_h(
    const float4* __restrict__ x, __half2* __restrict__ h, int n4)
{
    int i = blockIdx.x * 256 + threadIdx.x;
    if (i >= n4) return;
    float4 v = x[i];
    h[2 * i]     = __halves2half2(__float2half_rn(v.x), __float2half_rn(v.y));
    h[2 * i + 1] = __halves2half2(__float2half_rn(v.z), __float2half_rn(v.w));
}

// ---------------------------------------------------------------------------
// Transpose: w[K,N] fp32 -> hT[N,K] fp16
// ---------------------------------------------------------------------------
__global__ void cvt_trans_h(const float* __restrict__ w,
                            __half* __restrict__ h, int K, int N)
{
    __shared__ float t[32][33];
    int n0 = blockIdx.x * 32, k0 = blockIdx.y * 32;
    int tx = threadIdx.x, ty = threadIdx.y;
#pragma unroll
    for (int i = 0; i < 4; i++)
        t[ty + 8 * i][tx] = w[(size_t)(k0 + ty + 8 * i) * N + n0 + tx];
    __syncthreads();
#pragma unroll
    for (int i = 0; i < 4; i++) {
        float v = t[tx][ty + 8 * i];
        h[(size_t)(n0 + ty + 8 * i) * K + k0 + tx] = __float2half_rn(v);
    }
}

// ---------------------------------------------------------------------------
// fp16 HMMA GEMM:  C = A[M,K] @ B[N,K]^T + bias[N]
// CTA 128x128, 8 warps (2M x 4N), warp tile 64x32, KC=64,
// 3-stage cp.async, 2 CTAs/SM (110.6 KB smem each).
// out_mode: 0 = fp32 C; else fp16 Ch
// ---------------------------------------------------------------------------
#define KC       64
#define RSTRIDE  144
#define ARRB     (128 * RSTRIDE)         // 18432
#define STAGEB   (2 * ARRB)              // 36864 (A, B)
#define GSMEM    (3 * STAGEB)            // 110592

__device__ __forceinline__ void g_load_stage(
    uint32_t sb, int st, const __half* Ah, const __half* Bh,
    int m0, int n0, int k0, int K, int tid)
{
    uint32_t base = sb + (uint32_t)st * STAGEB;
#pragma unroll 2
    for (int i = tid; i < 2048; i += 256) {
        int arr = i >> 10;
        int idx = i & 1023;
        int row = idx >> 3;
        int c   = idx & 7;
        const __half* g = arr ? (Bh + (size_t)(n0 + row) * K)
                              : (Ah + (size_t)(m0 + row) * K);
        const __half* gp = g + k0 + c * 8;
        uint32_t sm = base + (uint32_t)arr * ARRB + (uint32_t)row * RSTRIDE + c * 16;
        CP_ASYNC16(sm, gp);
    }
}

__global__ __launch_bounds__(256, 2)
void gemm_fp16(const __half* __restrict__ Ah, const __half* __restrict__ Bh,
               const float* __restrict__ bias, float* __restrict__ C,
               __half* __restrict__ Ch, int M, int N, int K, int out_mode)
{
    extern __shared__ char smem[];
    uint32_t sb = smem_u32(smem);
    const int tid = threadIdx.x;
    const int wid = tid >> 5;
    const int lane = tid & 31;
    const int wm = wid & 1;
    const int wn = wid >> 1;
    const int m0 = blockIdx.y * 128;
    const int n0 = blockIdx.x * 128;

    float acc[4][4][4];
#pragma unroll
    for (int mi = 0; mi < 4; mi++)
#pragma unroll
        for (int ni = 0; ni < 4; ni++)
#pragma unroll
            for (int j = 0; j < 4; j++) acc[mi][ni][j] = 0.0f;

    const int S = K / KC;

    g_load_stage(sb, 0, Ah, Bh, m0, n0, 0, K, tid);
    CP_COMMIT();
    g_load_stage(sb, 1, Ah, Bh, m0, n0, KC, K, tid);
    CP_COMMIT();

    const int g8 = lane >> 3, r8 = lane & 7;
    const uint32_t aoff = (uint32_t)((wm * 64 + (g8 & 1) * 8 + r8) * RSTRIDE
                                     + (g8 >> 1) * 16);
    const uint32_t boff = (uint32_t)((wn * 32 + (g8 >> 1) * 8 + r8) * RSTRIDE
                                     + (g8 & 1) * 16);

    int buf = 0;
    for (int s = 0; s < S; s++) {
        if (s + 2 < S) {
            int pb = buf + 2; if (pb >= 3) pb -= 3;
            g_load_stage(sb, pb, Ah, Bh, m0, n0, (s + 2) * KC, K, tid);
            CP_COMMIT();
            CP_WAIT(2);
        } else if (s + 1 < S) {
            CP_WAIT(1);
        } else {
            CP_WAIT(0);
        }
        __syncthreads();

        uint32_t sA = sb + (uint32_t)buf * STAGEB;
        uint32_t sB = sA + ARRB;

#pragma unroll
        for (int ks = 0; ks < 4; ks++) {
            const uint32_t kb = ks * 32;
            uint32_t ah[4][4];
#pragma unroll
            for (int mi = 0; mi < 4; mi++) {
                uint32_t o = aoff + (uint32_t)(mi * 16 * RSTRIDE) + kb;
                ldm_x4(ah[mi], sA + o);
            }
            uint32_t bh[2][4];
#pragma unroll
            for (int nb = 0; nb < 2; nb++) {
                uint32_t o = boff + (uint32_t)(nb * 16 * RSTRIDE) + kb;
                ldm_x4(bh[nb], sB + o);
            }
#pragma unroll
            for (int mi = 0; mi < 4; mi++) {
#pragma unroll
                for (int ni = 0; ni < 4; ni++) {
                    const uint32_t* B2 = &bh[ni >> 1][(ni & 1) * 2];
                    mma16816(acc[mi][ni], ah[mi], B2);
                }
            }
        }
        __syncthreads();
        buf++; if (buf == 3) buf = 0;
    }

    const int er = lane >> 2;
    const int ec = (lane & 3) * 2;
#pragma unroll
    for (int mi = 0; mi < 4; mi++) {
        int row = m0 + wm * 64 + mi * 16 + er;
#pragma unroll
        for (int ni = 0; ni < 4; ni++) {
            int col = n0 + wn * 32 + ni * 8 + ec;
            float bx = bias[col], by = bias[col + 1];
            float v0 = acc[mi][ni][0] + bx, v1 = acc[mi][ni][1] + by;
            float v2 = acc[mi][ni][2] + bx, v3 = acc[mi][ni][3] + by;
            if (out_mode == 0) {
                *(float2*)(C + (size_t)row * N + col)       = make_float2(v0, v1);
                *(float2*)(C + (size_t)(row + 8) * N + col) = make_float2(v2, v3);
            } else {
                uint32_t hv0, hv1;
                { __half2 t2 = __halves2half2(__float2half_rn(v0), __float2half_rn(v1)); hv0 = *(uint32_t*)&t2; }
                { __half2 t2 = __halves2half2(__float2half_rn(v2), __float2half_rn(v3)); hv1 = *(uint32_t*)&t2; }
                *(uint32_t*)(Ch + (size_t)row * N + col)       = hv0;
                *(uint32_t*)(Ch + (size_t)(row + 8) * N + col) = hv1;
            }
        }
    }
}

// ---------------------------------------------------------------------------
// fp16 HMMA attention, sum-normalized softmax, pipelined K/V loads.
// S = Qh·Kh^T ;  X = Ph·Vh.  CTA = (b, h, 64 q-rows); 8 warps; 9 chunks.
// smem 110.8 KB -> 2 CTAs/SM.
// ---------------------------------------------------------------------------
#define AQS  528
#define APS  144
#define AT_Q   0
#define AT_K   (64 * AQS)
#define AT_V   (2 * 64 * AQS)
#define AT_PH  (3 * 64 * AQS)              // 101376
#define AT_RS  (AT_PH + 64 * APS)          // 110592
#define AT_SMEM (AT_RS + 64 * 4)           // 110848

__device__ __forceinline__ void at_load_k(
    uint32_t sb, const __half* kh, int b, int ch, size_t hc, int tid)
{
    for (int i = tid; i < 2048; i += 256) {
        int row = i >> 5, c = i & 31;
        const __half* g = kh + ((size_t)(b * LI + ch * 64 + row)) * HID + hc + c * 8;
        CP_ASYNC16(sb + AT_K + row * AQS + c * 16, g);
    }
}

__device__ __forceinline__ void at_load_v(
    uint32_t sb, const __half* vh, int b, int ch, size_t hc, int tid)
{
    for (int i = tid; i < 2048; i += 256) {
        int row = i >> 5, c = i & 31;
        const __half* g = vh + ((size_t)(b * LI + ch * 64 + row)) * HID + hc + c * 8;
        CP_ASYNC16(sb + AT_V + row * AQS + c * 16, g);
    }
}

__global__ __launch_bounds__(256, 2) void attn_hmma(
    const __half* __restrict__ qh, const __half* __restrict__ kh,
    const __half* __restrict__ vh, __half* __restrict__ xh)
{
    extern __shared__ char smem[];
    uint32_t sb = smem_u32(smem);
    float* rowsum = (float*)(smem + AT_RS);

    const int tid = threadIdx.x, lane = tid & 31, wid = tid >> 5;
    const int b = blockIdx.z, h = blockIdx.y;
    const int q0 = blockIdx.x * 64;
    const size_t hc = (size_t)h * HDIM;

    // Q and K0 (group 1), V0 (group 2)
    for (int i = tid; i < 2048; i += 256) {
        int row = i >> 5, c = i & 31;
        const __half* g = qh + ((size_t)(b * LT + q0 + row)) * HID + hc + c * 8;
        CP_ASYNC16(sb + AT_Q + row * AQS + c * 16, g);
    }
    at_load_k(sb, kh, b, 0, hc, tid);
    CP_COMMIT();
    at_load_v(sb, vh, b, 0, hc, tid);
    CP_COMMIT();

    if (tid < 64) rowsum[tid] = 0.0f;

    const int g8 = lane >> 3, r8 = lane & 7;
    const int wq = wid >> 1;
    const int wk = wid & 1;
    const int er = lane >> 2, ec2 = (lane & 3) * 2;

    const uint32_t aoA = (uint32_t)((wq * 16 + (g8 & 1) * 8 + r8) * AQS + (g8 >> 1) * 16);
    const uint32_t boB = (uint32_t)((wk * 32 + (g8 >> 1) * 8 + r8) * AQS + (g8 & 1) * 16);
    const uint32_t aoP = (uint32_t)((wq * 16 + (g8 & 1) * 8 + r8) * APS + (g8 >> 1) * 16);

    float acc2[16][4];
#pragma unroll
    for (int ni = 0; ni < 16; ni++)
#pragma unroll
        for (int j = 0; j < 4; j++) acc2[ni][j] = 0.0f;

    for (int ch = 0; ch < 9; ch++) {
        CP_WAIT(1);           // K(ch) (+Q on ch=0) complete
        __syncthreads();

        // ---- scores S[16q x 32keys] per warp ----
        float s[4][4];
#pragma unroll
        for (int ni = 0; ni < 4; ni++)
#pragma unroll
            for (int j = 0; j < 4; j++) s[ni][j] = 0.0f;

#pragma unroll 4
        for (int kk = 0; kk < 16; kk++) {
            uint32_t ka = kk * 32;
            uint32_t ahf[4];
            ldm_x4(ahf, sb + AT_Q + aoA + ka);
            uint32_t bhf[2][4];
#pragma unroll
            for (int nb = 0; nb < 2; nb++) {
                uint32_t o = boB + nb * 16 * AQS + ka;
                ldm_x4(bhf[nb], sb + AT_K + o);
            }
#pragma unroll
            for (int ni = 0; ni < 4; ni++) {
                const uint32_t* B2 = &bhf[ni >> 1][(ni & 1) * 2];
                mma16816(s[ni], ahf, B2);
            }
        }

        // ---- exp, row sums, P -> smem (fp16) ----
        float rs0 = 0.0f, rs1 = 0.0f;
#pragma unroll
        for (int ni = 0; ni < 4; ni++) {
            float p0 = __expf(s[ni][0] * 0.0625f);
            float p1 = __expf(s[ni][1] * 0.0625f);
            float p2 = __expf(s[ni][2] * 0.0625f);
            float p3 = __expf(s[ni][3] * 0.0625f);
            rs0 += p0 + p1;
            rs1 += p2 + p3;
            uint32_t hv0, hv1;
            { __half2 t2 = __halves2half2(__float2half_rn(p0), __float2half_rn(p1)); hv0 = *(uint32_t*)&t2; }
            { __half2 t2 = __halves2half2(__float2half_rn(p2), __float2half_rn(p3)); hv1 = *(uint32_t*)&t2; }
            int key = wk * 32 + ni * 8 + ec2;
            uint32_t po0 = (uint32_t)((wq * 16 + er) * APS + key * 2);
            uint32_t po1 = (uint32_t)((wq * 16 + er + 8) * APS + key * 2);
            *(uint32_t*)(smem + AT_PH + po0) = hv0;
            *(uint32_t*)(smem + AT_PH + po1) = hv1;
        }
        rs0 += __shfl_xor_sync(0xffffffffu, rs0, 1);
        rs0 += __shfl_xor_sync(0xffffffffu, rs0, 2);
        rs1 += __shfl_xor_sync(0xffffffffu, rs1, 1);
        rs1 += __shfl_xor_sync(0xffffffffu, rs1, 2);
        if ((lane & 3) == 0) {
            atomicAdd(&rowsum[wq * 16 + er], rs0);
            atomicAdd(&rowsum[wq * 16 + er + 8], rs1);
        }
        __syncthreads();      // P visible; K consumed by all warps

        // prefetch K(ch+1) over PV compute
        if (ch + 1 < 9) {
            at_load_k(sb, kh, b, ch + 1, hc, tid);
            CP_COMMIT();
            CP_WAIT(1);       // V(ch) complete (K(ch+1) may be in flight)
        } else {
            CP_WAIT(0);       // V(ch) complete
        }
        __syncthreads();      // V visible

        // ---- PV: X[16q x 128d] per warp over 64 keys ----
#pragma unroll
        for (int kk = 0; kk < 4; kk++) {
            uint32_t pa = kk * 32;
            uint32_t phf[4];
            ldm_x4(phf, sb + AT_PH + aoP + pa);
#pragma unroll
            for (int nb = 0; nb < 8; nb++) {
                int krow = kk * 16 + (g8 & 1) * 8 + r8;
                int dcol = wk * 128 + nb * 16 + (g8 >> 1) * 8;
                uint32_t vo = (uint32_t)(krow * AQS + dcol * 2);
                uint32_t bvh[4];
                ldm_x4t(bvh, sb + AT_V + vo);
                mma16816(acc2[2 * nb],     phf, &bvh[0]);
                mma16816(acc2[2 * nb + 1], phf, &bvh[2]);
            }
        }
        __syncthreads();      // V consumed by all warps

        // prefetch V(ch+1) over next QK compute
        if (ch + 1 < 9) {
            at_load_v(sb, vh, b, ch + 1, hc, tid);
            CP_COMMIT();
        }
    }

    // ---- normalize + write xh ----
    float inv0 = 1.0f / rowsum[wq * 16 + er];
    float inv1 = 1.0f / rowsum[wq * 16 + er + 8];
    size_t grow0 = ((size_t)(b * LT + q0 + wq * 16 + er)) * HID + hc;
    size_t grow1 = grow0 + (size_t)8 * HID;
#pragma unroll
    for (int ni = 0; ni < 16; ni++) {
        int col = wk * 128 + ni * 8 + ec2;
        float v0 = acc2[ni][0] * inv0, v1 = acc2[ni][1] * inv0;
        float v2 = acc2[ni][2] * inv1, v3 = acc2[ni][3] * inv1;
        uint32_t hv0, hv1;
        { __half2 t2 = __halves2half2(__float2half_rn(v0), __float2half_rn(v1)); hv0 = *(uint32_t*)&t2; }
        { __half2 t2 = __halves2half2(__float2half_rn(v2), __float2half_rn(v3)); hv1 = *(uint32_t*)&t2; }
        *(uint32_t*)(xh + grow0 + col) = hv0;
        *(uint32_t*)(xh + grow1 + col) = hv1;
    }
}

// ---------------------------------------------------------------------------
// Fused FF + residual + LayerNorm — 16 rows/block, dynamic smem.
// ---------------------------------------------------------------------------
#define FF_ROWS 16
#define FF_SMEM ((FF_ROWS*TEXTD + FF_ROWS*FFD + FF_ROWS*8*2 + FF_ROWS*2) * 4)

__global__ __launch_bounds__(256) void ffln_kernel(
    const float* __restrict__ O, const float* __restrict__ w1,
    const float* __restrict__ b1, const float* __restrict__ w2,
    const float* __restrict__ b2, const float* __restrict__ gamma,
    const float* __restrict__ beta, float* __restrict__ out)
{
    extern __shared__ float fsm[];
    float* xs   = fsm;
    float* hs   = xs + FF_ROWS * TEXTD;
    float* reds = hs + FF_ROWS * FFD;
    float* redq = reds + FF_ROWS * 8;
    float* s_mu = redq + FF_ROWS * 8;
    float* s_rs = s_mu + FF_ROWS;

    const int tid = threadIdx.x;
    const size_t row0 = (size_t)blockIdx.x * FF_ROWS;

    for (int i = tid; i < FF_ROWS * (TEXTD / 4); i += 256) {
        int r = i / (TEXTD / 4), c = (i % (TEXTD / 4)) * 4;
        *(float4*)&xs[r * TEXTD + c] = *(const float4*)(O + (row0 + r) * TEXTD + c);
    }
    __syncthreads();

    {
        const int u = tid & 127;
        const int rb = (tid >> 7) * 8;
        float a[8];
        float bb = b1[u];
#pragma unroll
        for (int j = 0; j < 8; j++) a[j] = bb;
        for (int dd = 0; dd < TEXTD; dd++) {
            float w = w1[dd * FFD + u];
#pragma unroll
            for (int j = 0; j < 8; j++) a[j] += xs[(rb + j) * TEXTD + dd] * w;
        }
#pragma unroll
        for (int j = 0; j < 8; j++) hs[(rb + j) * FFD + u] = fmaxf(a[j], 0.0f);
    }
    __syncthreads();

    float yv[FF_ROWS][3];
#pragma unroll
    for (int r = 0; r < FF_ROWS; r++)
#pragma unroll
        for (int c = 0; c < 3; c++) yv[r][c] = 0.0f;

    for (int u = 0; u < FFD; u++) {
        float wa = w2[(size_t)u * TEXTD + tid];
        float wb = w2[(size_t)u * TEXTD + tid + 256];
        float wc = w2[(size_t)u * TEXTD + tid + 512];
#pragma unroll
        for (int r = 0; r < FF_ROWS; r++) {
            float hv = hs[r * FFD + u];
            yv[r][0] += hv * wa;
            yv[r][1] += hv * wb;
            yv[r][2] += hv * wc;
        }
    }
#pragma unroll
    for (int r = 0; r < FF_ROWS; r++) {
#pragma unroll
        for (int c = 0; c < 3; c++) {
            int n = tid + c * 256;
            yv[r][c] += xs[r * TEXTD + n] + b2[n];
        }
    }

    const int lane = tid & 31, wd = tid >> 5;
#pragma unroll
    for (int r = 0; r < FF_ROWS; r++) {
        float s = yv[r][0] + yv[r][1] + yv[r][2];
        float q = yv[r][0] * yv[r][0] + yv[r][1] * yv[r][1] + yv[r][2] * yv[r][2];
#pragma unroll
        for (int o = 16; o; o >>= 1) {
            s += __shfl_xor_sync(0xffffffffu, s, o);
            q += __shfl_xor_sync(0xffffffffu, q, o);
        }
        if (lane == 0) { reds[r * 8 + wd] = s; redq[r * 8 + wd] = q; }
    }
    __syncthreads();
    if (tid < FF_ROWS) {
        float s = 0.0f, q = 0.0f;
#pragma unroll
        for (int w = 0; w < 8; w++) { s += reds[tid * 8 + w]; q += redq[tid * 8 + w]; }
        float m = s * (1.0f / TEXTD);
        float v = q * (1.0f / TEXTD) - m * m;
        s_mu[tid] = m;
        s_rs[tid] = rsqrtf(v + 1e-5f);
    }
    __syncthreads();

#pragma unroll
    for (int r = 0; r < FF_ROWS; r++) {
        float m = s_mu[r], rs = s_rs[r];
#pragma unroll
        for (int c = 0; c < 3; c++) {
            int n = tid + c * 256;
            out[(row0 + r) * TEXTD + n] = (yv[r][c] - m) * rs * gamma[n] + beta[n];
        }
    }
}

// ---------------------------------------------------------------------------
// Launcher
// ---------------------------------------------------------------------------
extern "C" void kernel_launch(void* const* d_in, const int* in_sizes, int n_in,
                              void* d_out, int out_size)
{
    const float* text  = (const float*)d_in[0];
    const float* image = (const float*)d_in[1];
    const float* wq = (const float*)d_in[2];
    const float* bq = (const float*)d_in[3];
    const float* wk = (const float*)d_in[4];
    const float* bk = (const float*)d_in[5];
    const float* wv = (const float*)d_in[6];
    const float* bv = (const float*)d_in[7];
    const float* wr = (const float*)d_in[8];
    const float* br = (const float*)d_in[9];
    const float* w1 = (const float*)d_in[10];
    const float* b1 = (const float*)d_in[11];
    const float* w2 = (const float*)d_in[12];
    const float* b2 = (const float*)d_in[13];
    const float* gamma = (const float*)d_in[14];
    const float* beta  = (const float*)d_in[15];
    float* out = (float*)d_out;

    float* Op;
    cudaGetSymbolAddress((void**)&Op, g_O);

    __half *th, *ih, *qh, *kh, *vh, *xh;
    __half *wqh, *wkh, *wvh, *wrh;
    cudaGetSymbolAddress((void**)&th, g_th);
    cudaGetSymbolAddress((void**)&ih, g_ih);
    cudaGetSymbolAddress((void**)&qh, g_qh);
    cudaGetSymbolAddress((void**)&kh, g_kh);
    cudaGetSymbolAddress((void**)&vh, g_vh);
    cudaGetSymbolAddress((void**)&xh, g_xh);
    cudaGetSymbolAddress((void**)&wqh, g_wqh);
    cudaGetSymbolAddress((void**)&wkh, g_wkh);
    cudaGetSymbolAddress((void**)&wvh, g_wvh);
    cudaGetSymbolAddress((void**)&wrh, g_wrh);

    cudaFuncSetAttribute(gemm_fp16, cudaFuncAttributeMaxDynamicSharedMemorySize,
                         GSMEM);
    cudaFuncSetAttribute(attn_hmma, cudaFuncAttributeMaxDynamicSharedMemorySize,
                         AT_SMEM);
    cudaFuncSetAttribute(ffln_kernel, cudaFuncAttributeMaxDynamicSharedMemorySize,
                         FF_SMEM);

    // --- conversions ---
    {
        int n4 = MQ * TEXTD / 4;
        cvt_h<<<(n4 + 255) / 256, 256>>>((const float4*)text, (__half2*)th, n4);
    }
    {
        int n4 = MK * IMGD / 4;
        cvt_h<<<(n4 + 255) / 256, 256>>>((const float4*)image, (__half2*)ih, n4);
    }
    cvt_trans_h<<<dim3(HID / 32, TEXTD / 32), dim3(32, 8)>>>(wq, wqh, TEXTD, HID);
    cvt_trans_h<<<dim3(HID / 32, IMGD / 32),  dim3(32, 8)>>>(wk, wkh, IMGD, HID);
    cvt_trans_h<<<dim3(HID / 32, IMGD / 32),  dim3(32, 8)>>>(wv, wvh, IMGD, HID);
    cvt_trans_h<<<dim3(TEXTD / 32, HID / 32), dim3(32, 8)>>>(wr, wrh, HID, TEXTD);

    // --- projection GEMMs -> fp16 ---
    gemm_fp16<<<dim3(HID / 128, MQ / 128), 256, GSMEM>>>(
        th, wqh, bq, nullptr, qh, MQ, HID, TEXTD, 1);
    gemm_fp16<<<dim3(HID / 128, MK / 128), 256, GSMEM>>>(
        ih, wkh, bk, nullptr, kh, MK, HID, IMGD, 1);
    gemm_fp16<<<dim3(HID / 128, MK / 128), 256, GSMEM>>>(
        ih, wvh, bv, nullptr, vh, MK, HID, IMGD, 1);

    // --- HMMA attention -> xh ---
    attn_hmma<<<dim3(LT / 64, HEADS, BATCH), 256, AT_SMEM>>>(qh, kh, vh, xh);

    // --- out projection -> fp32 ---
    gemm_fp16<<<dim3(TEXTD / 128, MQ / 128), 256, GSMEM>>>(
        xh, wrh, br, Op, nullptr, MQ, TEXTD, HID, 0);

    // --- FF + residual + LayerNorm ---
    ffln_kernel<<<MQ / FF_ROWS, 256, FF_SMEM>>>(Op, w1, b1, w2, b2, gamma, beta, out);
}

// round 14
// speedup vs baseline: 1.3158x; 1.3158x over previous
#include <cuda_runtime.h>
#include <cuda_fp16.h>
#include <math.h>
#include <stdint.h>

// ---------------------------------------------------------------------------
// Problem constants
// ---------------------------------------------------------------------------
#define BATCH   16
#define LT      512
#define LI      576
#define TEXTD   768
#define IMGD    1024
#define HID     2048
#define HEADS   8
#define HDIM    256
#define FFD     128

#define MQ (BATCH*LT)   // 8192
#define MK (BATCH*LI)   // 9216

// ---------------------------------------------------------------------------
// Device scratch (pure fp16 pipeline)
// ---------------------------------------------------------------------------
__device__ float g_O[(size_t)MQ * TEXTD];

__device__ __half g_th[(size_t)MQ * TEXTD];
__device__ __half g_ih[(size_t)MK * IMGD];
__device__ __half g_qh[(size_t)MQ * HID];
__device__ __half g_kh[(size_t)MK * HID];
__device__ __half g_vh[(size_t)MK * HID];
__device__ __half g_xh[(size_t)MQ * HID];
__device__ __half g_wqh[(size_t)HID * TEXTD];
__device__ __half g_wkh[(size_t)HID * IMGD];
__device__ __half g_wvh[(size_t)HID * IMGD];
__device__ __half g_wrh[(size_t)TEXTD * HID];

// ---------------------------------------------------------------------------
// PTX helpers
// ---------------------------------------------------------------------------
__device__ __forceinline__ uint32_t smem_u32(const void* p) {
    uint32_t a;
    asm("{ .reg .u64 t; cvta.to.shared.u64 t, %1; cvt.u32.u64 %0, t; }"
        : "=r"(a) : "l"(p));
    return a;
}

__device__ __forceinline__ void ldm_x4(uint32_t* r, uint32_t addr) {
    asm volatile("ldmatrix.sync.aligned.m8n8.x4.shared.b16 {%0,%1,%2,%3}, [%4];"
                 : "=r"(r[0]), "=r"(r[1]), "=r"(r[2]), "=r"(r[3]) : "r"(addr));
}

__device__ __forceinline__ void ldm_x4t(uint32_t* r, uint32_t addr) {
    asm volatile("ldmatrix.sync.aligned.m8n8.x4.trans.shared.b16 {%0,%1,%2,%3}, [%4];"
                 : "=r"(r[0]), "=r"(r[1]), "=r"(r[2]), "=r"(r[3]) : "r"(addr));
}

__device__ __forceinline__ void mma16816(float* d, const uint32_t* a,
                                         const uint32_t* b) {
    asm volatile(
        "mma.sync.aligned.m16n8k16.row.col.f32.f16.f16.f32 "
        "{%0,%1,%2,%3}, {%4,%5,%6,%7}, {%8,%9}, {%0,%1,%2,%3};"
        : "+f"(d[0]), "+f"(d[1]), "+f"(d[2]), "+f"(d[3])
        : "r"(a[0]), "r"(a[1]), "r"(a[2]), "r"(a[3]), "r"(b[0]), "r"(b[1]));
}

#define CP_ASYNC16(smem, gptr) \
    asm volatile("cp.async.cg.shared.global [%0], [%1], 16;" \
        :: "r"(smem), "l"(gptr) : "memory")
#define CP_COMMIT() asm volatile("cp.async.commit_group;" ::: "memory")
#define CP_WAIT(n)  asm volatile("cp.async.wait_group %0;" :: "n"(n) : "memory")

// ---------------------------------------------------------------------------
// fp32 -> fp16 convert (vectorized by 4)
// ---------------------------------------------------------------------------
__global__ __launch_bounds__(256) void cvt_h(
    const float4* __restrict__ x, __half2* __restrict__ h, int n4)
{
    int i = blockIdx.x * 256 + threadIdx.x;
    if (i >= n4) return;
    float4 v = x[i];
    h[2 * i]     = __halves2half2(__float2half_rn(v.x), __float2half_rn(v.y));
    h[2 * i + 1] = __halves2half2(__float2half_rn(v.z), __float2half_rn(v.w));
}

// ---------------------------------------------------------------------------
// Transpose: w[K,N] fp32 -> hT[N,K] fp16
// ---------------------------------------------------------------------------
__global__ void cvt_trans_h(const float* __restrict__ w,
                            __half* __restrict__ h, int K, int N)
{
    __shared__ float t[32][33];
    int n0 = blockIdx.x * 32, k0 = blockIdx.y * 32;
    int tx = threadIdx.x, ty = threadIdx.y;
#pragma unroll
    for (int i = 0; i < 4; i++)
        t[ty + 8 * i][tx] = w[(size_t)(k0 + ty + 8 * i) * N + n0 + tx];
    __syncthreads();
#pragma unroll
    for (int i = 0; i < 4; i++) {
        float v = t[tx][ty + 8 * i];
        h[(size_t)(n0 + ty + 8 * i) * K + k0 + tx] = __float2half_rn(v);
    }
}

// ---------------------------------------------------------------------------
// fp16 HMMA GEMM:  C = A[M,K] @ B[N,K]^T + bias[N]
// CTA 128x128, 8 warps (2M x 4N), warp tile 64x32, KC=64, 4-stage cp.async,
// 1 CTA/SM with full register budget (measured-best configuration).
// out_mode: 0 = fp32 C; else fp16 Ch
// ---------------------------------------------------------------------------
#define KC       64
#define RSTRIDE  144
#define ARRB     (128 * RSTRIDE)         // 18432
#define STAGEB   (2 * ARRB)              // 36864 (A, B)
#define GSMEM    (4 * STAGEB)            // 147456

__device__ __forceinline__ void g_load_stage(
    uint32_t sb, int st, const __half* Ah, const __half* Bh,
    int m0, int n0, int k0, int K, int tid)
{
    uint32_t base = sb + (uint32_t)st * STAGEB;
#pragma unroll 2
    for (int i = tid; i < 2048; i += 256) {
        int arr = i >> 10;
        int idx = i & 1023;
        int row = idx >> 3;
        int c   = idx & 7;
        const __half* g = arr ? (Bh + (size_t)(n0 + row) * K)
                              : (Ah + (size_t)(m0 + row) * K);
        const __half* gp = g + k0 + c * 8;
        uint32_t sm = base + (uint32_t)arr * ARRB + (uint32_t)row * RSTRIDE + c * 16;
        CP_ASYNC16(sm, gp);
    }
}

__global__ __launch_bounds__(256, 1)
void gemm_fp16(const __half* __restrict__ Ah, const __half* __restrict__ Bh,
               const float* __restrict__ bias, float* __restrict__ C,
               __half* __restrict__ Ch, int M, int N, int K, int out_mode)
{
    extern __shared__ char smem[];
    uint32_t sb = smem_u32(smem);
    const int tid = threadIdx.x;
    const int wid = tid >> 5;
    const int lane = tid & 31;
    const int wm = wid & 1;
    const int wn = wid >> 1;
    const int m0 = blockIdx.y * 128;
    const int n0 = blockIdx.x * 128;

    float acc[4][4][4];
#pragma unroll
    for (int mi = 0; mi < 4; mi++)
#pragma unroll
        for (int ni = 0; ni < 4; ni++)
#pragma unroll
            for (int j = 0; j < 4; j++) acc[mi][ni][j] = 0.0f;

    const int S = K / KC;

    g_load_stage(sb, 0, Ah, Bh, m0, n0, 0, K, tid);
    CP_COMMIT();
    g_load_stage(sb, 1, Ah, Bh, m0, n0, KC, K, tid);
    CP_COMMIT();
    g_load_stage(sb, 2, Ah, Bh, m0, n0, 2 * KC, K, tid);
    CP_COMMIT();

    const int g8 = lane >> 3, r8 = lane & 7;
    const uint32_t aoff = (uint32_t)((wm * 64 + (g8 & 1) * 8 + r8) * RSTRIDE
                                     + (g8 >> 1) * 16);
    const uint32_t boff = (uint32_t)((wn * 32 + (g8 >> 1) * 8 + r8) * RSTRIDE
                                     + (g8 & 1) * 16);

    for (int s = 0; s < S; s++) {
        int buf = s & 3;
        if (s + 3 < S) {
            g_load_stage(sb, (s + 3) & 3, Ah, Bh, m0, n0, (s + 3) * KC, K, tid);
            CP_COMMIT();
            CP_WAIT(3);
        } else if (s + 2 < S) {
            CP_WAIT(2);
        } else if (s + 1 < S) {
            CP_WAIT(1);
        } else {
            CP_WAIT(0);
        }
        __syncthreads();

        uint32_t sA = sb + (uint32_t)buf * STAGEB;
        uint32_t sB = sA + ARRB;

#pragma unroll
        for (int ks = 0; ks < 4; ks++) {
            const uint32_t kb = ks * 32;
            uint32_t ah[4][4];
#pragma unroll
            for (int mi = 0; mi < 4; mi++) {
                uint32_t o = aoff + (uint32_t)(mi * 16 * RSTRIDE) + kb;
                ldm_x4(ah[mi], sA + o);
            }
            uint32_t bh[2][4];
#pragma unroll
            for (int nb = 0; nb < 2; nb++) {
                uint32_t o = boff + (uint32_t)(nb * 16 * RSTRIDE) + kb;
                ldm_x4(bh[nb], sB + o);
            }
#pragma unroll
            for (int mi = 0; mi < 4; mi++) {
#pragma unroll
                for (int ni = 0; ni < 4; ni++) {
                    const uint32_t* B2 = &bh[ni >> 1][(ni & 1) * 2];
                    mma16816(acc[mi][ni], ah[mi], B2);
                }
            }
        }
        __syncthreads();
    }

    const int er = lane >> 2;
    const int ec = (lane & 3) * 2;
#pragma unroll
    for (int mi = 0; mi < 4; mi++) {
        int row = m0 + wm * 64 + mi * 16 + er;
#pragma unroll
        for (int ni = 0; ni < 4; ni++) {
            int col = n0 + wn * 32 + ni * 8 + ec;
            float bx = bias[col], by = bias[col + 1];
            float v0 = acc[mi][ni][0] + bx, v1 = acc[mi][ni][1] + by;
            float v2 = acc[mi][ni][2] + bx, v3 = acc[mi][ni][3] + by;
            if (out_mode == 0) {
                *(float2*)(C + (size_t)row * N + col)       = make_float2(v0, v1);
                *(float2*)(C + (size_t)(row + 8) * N + col) = make_float2(v2, v3);
            } else {
                uint32_t hv0, hv1;
                { __half2 t2 = __halves2half2(__float2half_rn(v0), __float2half_rn(v1)); hv0 = *(uint32_t*)&t2; }
                { __half2 t2 = __halves2half2(__float2half_rn(v2), __float2half_rn(v3)); hv1 = *(uint32_t*)&t2; }
                *(uint32_t*)(Ch + (size_t)row * N + col)       = hv0;
                *(uint32_t*)(Ch + (size_t)(row + 8) * N + col) = hv1;
            }
        }
    }
}

// ---------------------------------------------------------------------------
// fp16 HMMA attention, sum-normalized softmax, pipelined K/V loads.
// S = Qh·Kh^T ;  X = Ph·Vh.  CTA = (b, h, 64 q-rows); 8 warps; 9 chunks.
// smem 110.8 KB -> 2 CTAs/SM.
// ---------------------------------------------------------------------------
#define AQS  528
#define APS  144
#define AT_Q   0
#define AT_K   (64 * AQS)
#define AT_V   (2 * 64 * AQS)
#define AT_PH  (3 * 64 * AQS)              // 101376
#define AT_RS  (AT_PH + 64 * APS)          // 110592
#define AT_SMEM (AT_RS + 64 * 4)           // 110848

__device__ __forceinline__ void at_load_k(
    uint32_t sb, const __half* kh, int b, int ch, size_t hc, int tid)
{
    for (int i = tid; i < 2048; i += 256) {
        int row = i >> 5, c = i & 31;
        const __half* g = kh + ((size_t)(b * LI + ch * 64 + row)) * HID + hc + c * 8;
        CP_ASYNC16(sb + AT_K + row * AQS + c * 16, g);
    }
}

__device__ __forceinline__ void at_load_v(
    uint32_t sb, const __half* vh, int b, int ch, size_t hc, int tid)
{
    for (int i = tid; i < 2048; i += 256) {
        int row = i >> 5, c = i & 31;
        const __half* g = vh + ((size_t)(b * LI + ch * 64 + row)) * HID + hc + c * 8;
        CP_ASYNC16(sb + AT_V + row * AQS + c * 16, g);
    }
}

__global__ __launch_bounds__(256, 2) void attn_hmma(
    const __half* __restrict__ qh, const __half* __restrict__ kh,
    const __half* __restrict__ vh, __half* __restrict__ xh)
{
    extern __shared__ char smem[];
    uint32_t sb = smem_u32(smem);
    float* rowsum = (float*)(smem + AT_RS);

    const int tid = threadIdx.x, lane = tid & 31, wid = tid >> 5;
    const int b = blockIdx.z, h = blockIdx.y;
    const int q0 = blockIdx.x * 64;
    const size_t hc = (size_t)h * HDIM;

    // Q and K0 (group 1), V0 (group 2)
    for (int i = tid; i < 2048; i += 256) {
        int row = i >> 5, c = i & 31;
        const __half* g = qh + ((size_t)(b * LT + q0 + row)) * HID + hc + c * 8;
        CP_ASYNC16(sb + AT_Q + row * AQS + c * 16, g);
    }
    at_load_k(sb, kh, b, 0, hc, tid);
    CP_COMMIT();
    at_load_v(sb, vh, b, 0, hc, tid);
    CP_COMMIT();

    if (tid < 64) rowsum[tid] = 0.0f;

    const int g8 = lane >> 3, r8 = lane & 7;
    const int wq = wid >> 1;
    const int wk = wid & 1;
    const int er = lane >> 2, ec2 = (lane & 3) * 2;

    const uint32_t aoA = (uint32_t)((wq * 16 + (g8 & 1) * 8 + r8) * AQS + (g8 >> 1) * 16);
    const uint32_t boB = (uint32_t)((wk * 32 + (g8 >> 1) * 8 + r8) * AQS + (g8 & 1) * 16);
    const uint32_t aoP = (uint32_t)((wq * 16 + (g8 & 1) * 8 + r8) * APS + (g8 >> 1) * 16);

    float acc2[16][4];
#pragma unroll
    for (int ni = 0; ni < 16; ni++)
#pragma unroll
        for (int j = 0; j < 4; j++) acc2[ni][j] = 0.0f;

    for (int ch = 0; ch < 9; ch++) {
        CP_WAIT(1);           // K(ch) (+Q on ch=0) complete
        __syncthreads();

        // ---- scores S[16q x 32keys] per warp ----
        float s[4][4];
#pragma unroll
        for (int ni = 0; ni < 4; ni++)
#pragma unroll
            for (int j = 0; j < 4; j++) s[ni][j] = 0.0f;

#pragma unroll 4
        for (int kk = 0; kk < 16; kk++) {
            uint32_t ka = kk * 32;
            uint32_t ahf[4];
            ldm_x4(ahf, sb + AT_Q + aoA + ka);
            uint32_t bhf[2][4];
#pragma unroll
            for (int nb = 0; nb < 2; nb++) {
                uint32_t o = boB + nb * 16 * AQS + ka;
                ldm_x4(bhf[nb], sb + AT_K + o);
            }
#pragma unroll
            for (int ni = 0; ni < 4; ni++) {
                const uint32_t* B2 = &bhf[ni >> 1][(ni & 1) * 2];
                mma16816(s[ni], ahf, B2);
            }
        }

        // ---- exp, row sums, P -> smem (fp16) ----
        float rs0 = 0.0f, rs1 = 0.0f;
#pragma unroll
        for (int ni = 0; ni < 4; ni++) {
            float p0 = __expf(s[ni][0] * 0.0625f);
            float p1 = __expf(s[ni][1] * 0.0625f);
            float p2 = __expf(s[ni][2] * 0.0625f);
            float p3 = __expf(s[ni][3] * 0.0625f);
            rs0 += p0 + p1;
            rs1 += p2 + p3;
            uint32_t hv0, hv1;
            { __half2 t2 = __halves2half2(__float2half_rn(p0), __float2half_rn(p1)); hv0 = *(uint32_t*)&t2; }
            { __half2 t2 = __halves2half2(__float2half_rn(p2), __float2half_rn(p3)); hv1 = *(uint32_t*)&t2; }
            int key = wk * 32 + ni * 8 + ec2;
            uint32_t po0 = (uint32_t)((wq * 16 + er) * APS + key * 2);
            uint32_t po1 = (uint32_t)((wq * 16 + er + 8) * APS + key * 2);
            *(uint32_t*)(smem + AT_PH + po0) = hv0;
            *(uint32_t*)(smem + AT_PH + po1) = hv1;
        }
        rs0 += __shfl_xor_sync(0xffffffffu, rs0, 1);
        rs0 += __shfl_xor_sync(0xffffffffu, rs0, 2);
        rs1 += __shfl_xor_sync(0xffffffffu, rs1, 1);
        rs1 += __shfl_xor_sync(0xffffffffu, rs1, 2);
        if ((lane & 3) == 0) {
            atomicAdd(&rowsum[wq * 16 + er], rs0);
            atomicAdd(&rowsum[wq * 16 + er + 8], rs1);
        }
        __syncthreads();      // P visible; K consumed by all warps

        // prefetch K(ch+1) over PV compute
        if (ch + 1 < 9) {
            at_load_k(sb, kh, b, ch + 1, hc, tid);
            CP_COMMIT();
            CP_WAIT(1);       // V(ch) complete (K(ch+1) may be in flight)
        } else {
            CP_WAIT(0);       // V(ch) complete
        }
        __syncthreads();      // V visible

        // ---- PV: X[16q x 128d] per warp over 64 keys ----
#pragma unroll
        for (int kk = 0; kk < 4; kk++) {
            uint32_t pa = kk * 32;
            uint32_t phf[4];
            ldm_x4(phf, sb + AT_PH + aoP + pa);
#pragma unroll
            for (int nb = 0; nb < 8; nb++) {
                int krow = kk * 16 + (g8 & 1) * 8 + r8;
                int dcol = wk * 128 + nb * 16 + (g8 >> 1) * 8;
                uint32_t vo = (uint32_t)(krow * AQS + dcol * 2);
                uint32_t bvh[4];
                ldm_x4t(bvh, sb + AT_V + vo);
                mma16816(acc2[2 * nb],     phf, &bvh[0]);
                mma16816(acc2[2 * nb + 1], phf, &bvh[2]);
            }
        }
        __syncthreads();      // V consumed by all warps

        // prefetch V(ch+1) over next QK compute
        if (ch + 1 < 9) {
            at_load_v(sb, vh, b, ch + 1, hc, tid);
            CP_COMMIT();
        }
    }

    // ---- normalize + write xh ----
    float inv0 = 1.0f / rowsum[wq * 16 + er];
    float inv1 = 1.0f / rowsum[wq * 16 + er + 8];
    size_t grow0 = ((size_t)(b * LT + q0 + wq * 16 + er)) * HID + hc;
    size_t grow1 = grow0 + (size_t)8 * HID;
#pragma unroll
    for (int ni = 0; ni < 16; ni++) {
        int col = wk * 128 + ni * 8 + ec2;
        float v0 = acc2[ni][0] * inv0, v1 = acc2[ni][1] * inv0;
        float v2 = acc2[ni][2] * inv1, v3 = acc2[ni][3] * inv1;
        uint32_t hv0, hv1;
        { __half2 t2 = __halves2half2(__float2half_rn(v0), __float2half_rn(v1)); hv0 = *(uint32_t*)&t2; }
        { __half2 t2 = __halves2half2(__float2half_rn(v2), __float2half_rn(v3)); hv1 = *(uint32_t*)&t2; }
        *(uint32_t*)(xh + grow0 + col) = hv0;
        *(uint32_t*)(xh + grow1 + col) = hv1;
    }
}

// ---------------------------------------------------------------------------
// Fused FF + residual + LayerNorm — 16 rows/block, dynamic smem.
// ---------------------------------------------------------------------------
#define FF_ROWS 16
#define FF_SMEM ((FF_ROWS*TEXTD + FF_ROWS*FFD + FF_ROWS*8*2 + FF_ROWS*2) * 4)

__global__ __launch_bounds__(256) void ffln_kernel(
    const float* __restrict__ O, const float* __restrict__ w1,
    const float* __restrict__ b1, const float* __restrict__ w2,
    const float* __restrict__ b2, const float* __restrict__ gamma,
    const float* __restrict__ beta, float* __restrict__ out)
{
    extern __shared__ float fsm[];
    float* xs   = fsm;
    float* hs   = xs + FF_ROWS * TEXTD;
    float* reds = hs + FF_ROWS * FFD;
    float* redq = reds + FF_ROWS * 8;
    float* s_mu = redq + FF_ROWS * 8;
    float* s_rs = s_mu + FF_ROWS;

    const int tid = threadIdx.x;
    const size_t row0 = (size_t)blockIdx.x * FF_ROWS;

    for (int i = tid; i < FF_ROWS * (TEXTD / 4); i += 256) {
        int r = i / (TEXTD / 4), c = (i % (TEXTD / 4)) * 4;
        *(float4*)&xs[r * TEXTD + c] = *(const float4*)(O + (row0 + r) * TEXTD + c);
    }
    __syncthreads();

    {
        const int u = tid & 127;
        const int rb = (tid >> 7) * 8;
        float a[8];
        float bb = b1[u];
#pragma unroll
        for (int j = 0; j < 8; j++) a[j] = bb;
        for (int dd = 0; dd < TEXTD; dd++) {
            float w = w1[dd * FFD + u];
#pragma unroll
            for (int j = 0; j < 8; j++) a[j] += xs[(rb + j) * TEXTD + dd] * w;
        }
#pragma unroll
        for (int j = 0; j < 8; j++) hs[(rb + j) * FFD + u] = fmaxf(a[j], 0.0f);
    }
    __syncthreads();

    float yv[FF_ROWS][3];
#pragma unroll
    for (int r = 0; r < FF_ROWS; r++)
#pragma unroll
        for (int c = 0; c < 3; c++) yv[r][c] = 0.0f;

    for (int u = 0; u < FFD; u++) {
        float wa = w2[(size_t)u * TEXTD + tid];
        float wb = w2[(size_t)u * TEXTD + tid + 256];
        float wc = w2[(size_t)u * TEXTD + tid + 512];
#pragma unroll
        for (int r = 0; r < FF_ROWS; r++) {
            float hv = hs[r * FFD + u];
            yv[r][0] += hv * wa;
            yv[r][1] += hv * wb;
            yv[r][2] += hv * wc;
        }
    }
#pragma unroll
    for (int r = 0; r < FF_ROWS; r++) {
#pragma unroll
        for (int c = 0; c < 3; c++) {
            int n = tid + c * 256;
            yv[r][c] += xs[r * TEXTD + n] + b2[n];
        }
    }

    const int lane = tid & 31, wd = tid >> 5;
#pragma unroll
    for (int r = 0; r < FF_ROWS; r++) {
        float s = yv[r][0] + yv[r][1] + yv[r][2];
        float q = yv[r][0] * yv[r][0] + yv[r][1] * yv[r][1] + yv[r][2] * yv[r][2];
#pragma unroll
        for (int o = 16; o; o >>= 1) {
            s += __shfl_xor_sync(0xffffffffu, s, o);
            q += __shfl_xor_sync(0xffffffffu, q, o);
        }
        if (lane == 0) { reds[r * 8 + wd] = s; redq[r * 8 + wd] = q; }
    }
    __syncthreads();
    if (tid < FF_ROWS) {
        float s = 0.0f, q = 0.0f;
#pragma unroll
        for (int w = 0; w < 8; w++) { s += reds[tid * 8 + w]; q += redq[tid * 8 + w]; }
        float m = s * (1.0f / TEXTD);
        float v = q * (1.0f / TEXTD) - m * m;
        s_mu[tid] = m;
        s_rs[tid] = rsqrtf(v + 1e-5f);
    }
    __syncthreads();

#pragma unroll
    for (int r = 0; r < FF_ROWS; r++) {
        float m = s_mu[r], rs = s_rs[r];
#pragma unroll
        for (int c = 0; c < 3; c++) {
            int n = tid + c * 256;
            out[(row0 + r) * TEXTD + n] = (yv[r][c] - m) * rs * gamma[n] + beta[n];
        }
    }
}

// ---------------------------------------------------------------------------
// Launcher
// ---------------------------------------------------------------------------
extern "C" void kernel_launch(void* const* d_in, const int* in_sizes, int n_in,
                              void* d_out, int out_size)
{
    const float* text  = (const float*)d_in[0];
    const float* image = (const float*)d_in[1];
    const float* wq = (const float*)d_in[2];
    const float* bq = (const float*)d_in[3];
    const float* wk = (const float*)d_in[4];
    const float* bk = (const float*)d_in[5];
    const float* wv = (const float*)d_in[6];
    const float* bv = (const float*)d_in[7];
    const float* wr = (const float*)d_in[8];
    const float* br = (const float*)d_in[9];
    const float* w1 = (const float*)d_in[10];
    const float* b1 = (const float*)d_in[11];
    const float* w2 = (const float*)d_in[12];
    const float* b2 = (const float*)d_in[13];
    const float* gamma = (const float*)d_in[14];
    const float* beta  = (const float*)d_in[15];
    float* out = (float*)d_out;

    float* Op;
    cudaGetSymbolAddress((void**)&Op, g_O);

    __half *th, *ih, *qh, *kh, *vh, *xh;
    __half *wqh, *wkh, *wvh, *wrh;
    cudaGetSymbolAddress((void**)&th, g_th);
    cudaGetSymbolAddress((void**)&ih, g_ih);
    cudaGetSymbolAddress((void**)&qh, g_qh);
    cudaGetSymbolAddress((void**)&kh, g_kh);
    cudaGetSymbolAddress((void**)&vh, g_vh);
    cudaGetSymbolAddress((void**)&xh, g_xh);
    cudaGetSymbolAddress((void**)&wqh, g_wqh);
    cudaGetSymbolAddress((void**)&wkh, g_wkh);
    cudaGetSymbolAddress((void**)&wvh, g_wvh);
    cudaGetSymbolAddress((void**)&wrh, g_wrh);

    cudaFuncSetAttribute(gemm_fp16, cudaFuncAttributeMaxDynamicSharedMemorySize,
                         GSMEM);
    cudaFuncSetAttribute(attn_hmma, cudaFuncAttributeMaxDynamicSharedMemorySize,
                         AT_SMEM);
    cudaFuncSetAttribute(ffln_kernel, cudaFuncAttributeMaxDynamicSharedMemorySize,
                         FF_SMEM);

    // --- conversions ---
    {
        int n4 = MQ * TEXTD / 4;
        cvt_h<<<(n4 + 255) / 256, 256>>>((const float4*)text, (__half2*)th, n4);
    }
    {
        int n4 = MK * IMGD / 4;
        cvt_h<<<(n4 + 255) / 256, 256>>>((const float4*)image, (__half2*)ih, n4);
    }
    cvt_trans_h<<<dim3(HID / 32, TEXTD / 32), dim3(32, 8)>>>(wq, wqh, TEXTD, HID);
    cvt_trans_h<<<dim3(HID / 32, IMGD / 32),  dim3(32, 8)>>>(wk, wkh, IMGD, HID);
    cvt_trans_h<<<dim3(HID / 32, IMGD / 32),  dim3(32, 8)>>>(wv, wvh, IMGD, HID);
    cvt_trans_h<<<dim3(TEXTD / 32, HID / 32), dim3(32, 8)>>>(wr, wrh, HID, TEXTD);

    // --- projection GEMMs -> fp16 ---
    gemm_fp16<<<dim3(HID / 128, MQ / 128), 256, GSMEM>>>(
        th, wqh, bq, nullptr, qh, MQ, HID, TEXTD, 1);
    gemm_fp16<<<dim3(HID / 128, MK / 128), 256, GSMEM>>>(
        ih, wkh, bk, nullptr, kh, MK, HID, IMGD, 1);
    gemm_fp16<<<dim3(HID / 128, MK / 128), 256, GSMEM>>>(
        ih, wvh, bv, nullptr, vh, MK, HID, IMGD, 1);

    // --- HMMA attention -> xh ---
    attn_hmma<<<dim3(LT / 64, HEADS, BATCH), 256, AT_SMEM>>>(qh, kh, vh, xh);

    // --- out projection -> fp32 ---
    gemm_fp16<<<dim3(TEXTD / 128, MQ / 128), 256, GSMEM>>>(
        xh, wrh, br, Op, nullptr, MQ, TEXTD, HID, 0);

    // --- FF + residual + LayerNorm ---
    ffln_kernel<<<MQ / FF_ROWS, 256, FF_SMEM>>>(Op, w1, b1, w2, b2, gamma, beta, out);
}

// round 15
// speedup vs baseline: 1.5345x; 1.1662x over previous
#include <cuda_runtime.h>
#include <cuda_fp16.h>
#include <math.h>
#include <stdint.h>

// ---------------------------------------------------------------------------
// Problem constants
// ---------------------------------------------------------------------------
#define BATCH   16
#define LT      512
#define LI      576
#define TEXTD   768
#define IMGD    1024
#define HID     2048
#define HEADS   8
#define HDIM    256
#define FFD     128

#define MQ (BATCH*LT)   // 8192
#define MK (BATCH*LI)   // 9216

// ---------------------------------------------------------------------------
// Device scratch (pure fp16 pipeline)
// ---------------------------------------------------------------------------
__device__ float g_O[(size_t)MQ * TEXTD];
__device__ float g_Y[(size_t)MQ * TEXTD];

__device__ __half g_th[(size_t)MQ * TEXTD];
__device__ __half g_ih[(size_t)MK * IMGD];
__device__ __half g_qh[(size_t)MQ * HID];
__device__ __half g_kh[(size_t)MK * HID];
__device__ __half g_vh[(size_t)MK * HID];
__device__ __half g_xh[(size_t)MQ * HID];
__device__ __half g_oh[(size_t)MQ * TEXTD];
__device__ __half g_hh[(size_t)MQ * FFD];
__device__ __half g_wqh[(size_t)HID * TEXTD];
__device__ __half g_wkh[(size_t)HID * IMGD];
__device__ __half g_wvh[(size_t)HID * IMGD];
__device__ __half g_wrh[(size_t)TEXTD * HID];
__device__ __half g_w1h[(size_t)FFD * TEXTD];
__device__ __half g_w2h[(size_t)TEXTD * FFD];

// ---------------------------------------------------------------------------
// PTX helpers
// ---------------------------------------------------------------------------
__device__ __forceinline__ uint32_t smem_u32(const void* p) {
    uint32_t a;
    asm("{ .reg .u64 t; cvta.to.shared.u64 t, %1; cvt.u32.u64 %0, t; }"
        : "=r"(a) : "l"(p));
    return a;
}

__device__ __forceinline__ void ldm_x4(uint32_t* r, uint32_t addr) {
    asm volatile("ldmatrix.sync.aligned.m8n8.x4.shared.b16 {%0,%1,%2,%3}, [%4];"
                 : "=r"(r[0]), "=r"(r[1]), "=r"(r[2]), "=r"(r[3]) : "r"(addr));
}

__device__ __forceinline__ void ldm_x4t(uint32_t* r, uint32_t addr) {
    asm volatile("ldmatrix.sync.aligned.m8n8.x4.trans.shared.b16 {%0,%1,%2,%3}, [%4];"
                 : "=r"(r[0]), "=r"(r[1]), "=r"(r[2]), "=r"(r[3]) : "r"(addr));
}

__device__ __forceinline__ void mma16816(float* d, const uint32_t* a,
                                         const uint32_t* b) {
    asm volatile(
        "mma.sync.aligned.m16n8k16.row.col.f32.f16.f16.f32 "
        "{%0,%1,%2,%3}, {%4,%5,%6,%7}, {%8,%9}, {%0,%1,%2,%3};"
        : "+f"(d[0]), "+f"(d[1]), "+f"(d[2]), "+f"(d[3])
        : "r"(a[0]), "r"(a[1]), "r"(a[2]), "r"(a[3]), "r"(b[0]), "r"(b[1]));
}

#define CP_ASYNC16(smem, gptr) \
    asm volatile("cp.async.cg.shared.global [%0], [%1], 16;" \
        :: "r"(smem), "l"(gptr) : "memory")
#define CP_COMMIT() asm volatile("cp.async.commit_group;" ::: "memory")
#define CP_WAIT(n)  asm volatile("cp.async.wait_group %0;" :: "n"(n) : "memory")

// ---------------------------------------------------------------------------
// fp32 -> fp16 convert (vectorized by 4)
// ---------------------------------------------------------------------------
__global__ __launch_bounds__(256) void cvt_h(
    const float4* __restrict__ x, __half2* __restrict__ h, int n4)
{
    int i = blockIdx.x * 256 + threadIdx.x;
    if (i >= n4) return;
    float4 v = x[i];
    h[2 * i]     = __halves2half2(__float2half_rn(v.x), __float2half_rn(v.y));
    h[2 * i + 1] = __halves2half2(__float2half_rn(v.z), __float2half_rn(v.w));
}

// ---------------------------------------------------------------------------
// Transpose: w[K,N] fp32 -> hT[N,K] fp16
// ---------------------------------------------------------------------------
__global__ void cvt_trans_h(const float* __restrict__ w,
                            __half* __restrict__ h, int K, int N)
{
    __shared__ float t[32][33];
    int n0 = blockIdx.x * 32, k0 = blockIdx.y * 32;
    int tx = threadIdx.x, ty = threadIdx.y;
#pragma unroll
    for (int i = 0; i < 4; i++)
        t[ty + 8 * i][tx] = w[(size_t)(k0 + ty + 8 * i) * N + n0 + tx];
    __syncthreads();
#pragma unroll
    for (int i = 0; i < 4; i++) {
        float v = t[tx][ty + 8 * i];
        h[(size_t)(n0 + ty + 8 * i) * K + k0 + tx] = __float2half_rn(v);
    }
}

// ---------------------------------------------------------------------------
// fp16 HMMA GEMM:  C = A[M,K] @ B[N,K]^T + bias[N]
// CTA 128x128, 8 warps (2M x 4N), warp tile 64x32, KC=64, 4-stage cp.async,
// 1 CTA/SM with full register budget (measured-best configuration).
// out_mode: 0 = fp32 C; 1 = fp16 Ch; 2 = fp32 C AND fp16 Ch; 3 = relu->fp16 Ch
// ---------------------------------------------------------------------------
#define KC       64
#define RSTRIDE  144
#define ARRB     (128 * RSTRIDE)         // 18432
#define STAGEB   (2 * ARRB)              // 36864 (A, B)
#define GSMEM    (4 * STAGEB)            // 147456

__device__ __forceinline__ void g_load_stage(
    uint32_t sb, int st, const __half* Ah, const __half* Bh,
    int m0, int n0, int k0, int K, int tid)
{
    uint32_t base = sb + (uint32_t)st * STAGEB;
#pragma unroll 2
    for (int i = tid; i < 2048; i += 256) {
        int arr = i >> 10;
        int idx = i & 1023;
        int row = idx >> 3;
        int c   = idx & 7;
        const __half* g = arr ? (Bh + (size_t)(n0 + row) * K)
                              : (Ah + (size_t)(m0 + row) * K);
        const __half* gp = g + k0 + c * 8;
        uint32_t sm = base + (uint32_t)arr * ARRB + (uint32_t)row * RSTRIDE + c * 16;
        CP_ASYNC16(sm, gp);
    }
}

__global__ __launch_bounds__(256, 1)
void gemm_fp16(const __half* __restrict__ Ah, const __half* __restrict__ Bh,
               const float* __restrict__ bias, float* __restrict__ C,
               __half* __restrict__ Ch, int M, int N, int K, int out_mode)
{
    extern __shared__ char smem[];
    uint32_t sb = smem_u32(smem);
    const int tid = threadIdx.x;
    const int wid = tid >> 5;
    const int lane = tid & 31;
    const int wm = wid & 1;
    const int wn = wid >> 1;
    const int m0 = blockIdx.y * 128;
    const int n0 = blockIdx.x * 128;

    float acc[4][4][4];
#pragma unroll
    for (int mi = 0; mi < 4; mi++)
#pragma unroll
        for (int ni = 0; ni < 4; ni++)
#pragma unroll
            for (int j = 0; j < 4; j++) acc[mi][ni][j] = 0.0f;

    const int S = K / KC;

    g_load_stage(sb, 0, Ah, Bh, m0, n0, 0, K, tid);
    CP_COMMIT();
    if (S > 1) {
        g_load_stage(sb, 1, Ah, Bh, m0, n0, KC, K, tid);
        CP_COMMIT();
    }
    if (S > 2) {
        g_load_stage(sb, 2, Ah, Bh, m0, n0, 2 * KC, K, tid);
        CP_COMMIT();
    }

    const int g8 = lane >> 3, r8 = lane & 7;
    const uint32_t aoff = (uint32_t)((wm * 64 + (g8 & 1) * 8 + r8) * RSTRIDE
                                     + (g8 >> 1) * 16);
    const uint32_t boff = (uint32_t)((wn * 32 + (g8 >> 1) * 8 + r8) * RSTRIDE
                                     + (g8 & 1) * 16);

    for (int s = 0; s < S; s++) {
        int buf = s & 3;
        if (s + 3 < S) {
            g_load_stage(sb, (s + 3) & 3, Ah, Bh, m0, n0, (s + 3) * KC, K, tid);
            CP_COMMIT();
            CP_WAIT(3);
        } else if (s + 2 < S) {
            CP_WAIT(2);
        } else if (s + 1 < S) {
            CP_WAIT(1);
        } else {
            CP_WAIT(0);
        }
        __syncthreads();

        uint32_t sA = sb + (uint32_t)buf * STAGEB;
        uint32_t sB = sA + ARRB;

#pragma unroll
        for (int ks = 0; ks < 4; ks++) {
            const uint32_t kb = ks * 32;
            uint32_t ah[4][4];
#pragma unroll
            for (int mi = 0; mi < 4; mi++) {
                uint32_t o = aoff + (uint32_t)(mi * 16 * RSTRIDE) + kb;
                ldm_x4(ah[mi], sA + o);
            }
            uint32_t bh[2][4];
#pragma unroll
            for (int nb = 0; nb < 2; nb++) {
                uint32_t o = boff + (uint32_t)(nb * 16 * RSTRIDE) + kb;
                ldm_x4(bh[nb], sB + o);
            }
#pragma unroll
            for (int mi = 0; mi < 4; mi++) {
#pragma unroll
                for (int ni = 0; ni < 4; ni++) {
                    const uint32_t* B2 = &bh[ni >> 1][(ni & 1) * 2];
                    mma16816(acc[mi][ni], ah[mi], B2);
                }
            }
        }
        __syncthreads();
    }

    const int er = lane >> 2;
    const int ec = (lane & 3) * 2;
#pragma unroll
    for (int mi = 0; mi < 4; mi++) {
        int row = m0 + wm * 64 + mi * 16 + er;
#pragma unroll
        for (int ni = 0; ni < 4; ni++) {
            int col = n0 + wn * 32 + ni * 8 + ec;
            float bx = bias[col], by = bias[col + 1];
            float v0 = acc[mi][ni][0] + bx, v1 = acc[mi][ni][1] + by;
            float v2 = acc[mi][ni][2] + bx, v3 = acc[mi][ni][3] + by;
            if (out_mode == 3) {
                v0 = fmaxf(v0, 0.0f); v1 = fmaxf(v1, 0.0f);
                v2 = fmaxf(v2, 0.0f); v3 = fmaxf(v3, 0.0f);
            }
            if (out_mode == 0 || out_mode == 2) {
                *(float2*)(C + (size_t)row * N + col)       = make_float2(v0, v1);
                *(float2*)(C + (size_t)(row + 8) * N + col) = make_float2(v2, v3);
            }
            if (out_mode != 0) {
                uint32_t hv0, hv1;
                { __half2 t2 = __halves2half2(__float2half_rn(v0), __float2half_rn(v1)); hv0 = *(uint32_t*)&t2; }
                { __half2 t2 = __halves2half2(__float2half_rn(v2), __float2half_rn(v3)); hv1 = *(uint32_t*)&t2; }
                *(uint32_t*)(Ch + (size_t)row * N + col)       = hv0;
                *(uint32_t*)(Ch + (size_t)(row + 8) * N + col) = hv1;
            }
        }
    }
}

// ---------------------------------------------------------------------------
// fp16 HMMA attention, sum-normalized softmax, pipelined K/V loads.
// S = Qh·Kh^T ;  X = Ph·Vh.  CTA = (b, h, 64 q-rows); 8 warps; 9 chunks.
// smem 110.8 KB -> 2 CTAs/SM.
// ---------------------------------------------------------------------------
#define AQS  528
#define APS  144
#define AT_Q   0
#define AT_K   (64 * AQS)
#define AT_V   (2 * 64 * AQS)
#define AT_PH  (3 * 64 * AQS)              // 101376
#define AT_RS  (AT_PH + 64 * APS)          // 110592
#define AT_SMEM (AT_RS + 64 * 4)           // 110848

__device__ __forceinline__ void at_load_k(
    uint32_t sb, const __half* kh, int b, int ch, size_t hc, int tid)
{
    for (int i = tid; i < 2048; i += 256) {
        int row = i >> 5, c = i & 31;
        const __half* g = kh + ((size_t)(b * LI + ch * 64 + row)) * HID + hc + c * 8;
        CP_ASYNC16(sb + AT_K + row * AQS + c * 16, g);
    }
}

__device__ __forceinline__ void at_load_v(
    uint32_t sb, const __half* vh, int b, int ch, size_t hc, int tid)
{
    for (int i = tid; i < 2048; i += 256) {
        int row = i >> 5, c = i & 31;
        const __half* g = vh + ((size_t)(b * LI + ch * 64 + row)) * HID + hc + c * 8;
        CP_ASYNC16(sb + AT_V + row * AQS + c * 16, g);
    }
}

__global__ __launch_bounds__(256, 2) void attn_hmma(
    const __half* __restrict__ qh, const __half* __restrict__ kh,
    const __half* __restrict__ vh, __half* __restrict__ xh)
{
    extern __shared__ char smem[];
    uint32_t sb = smem_u32(smem);
    float* rowsum = (float*)(smem + AT_RS);

    const int tid = threadIdx.x, lane = tid & 31, wid = tid >> 5;
    const int b = blockIdx.z, h = blockIdx.y;
    const int q0 = blockIdx.x * 64;
    const size_t hc = (size_t)h * HDIM;

    // Q and K0 (group 1), V0 (group 2)
    for (int i = tid; i < 2048; i += 256) {
        int row = i >> 5, c = i & 31;
        const __half* g = qh + ((size_t)(b * LT + q0 + row)) * HID + hc + c * 8;
        CP_ASYNC16(sb + AT_Q + row * AQS + c * 16, g);
    }
    at_load_k(sb, kh, b, 0, hc, tid);
    CP_COMMIT();
    at_load_v(sb, vh, b, 0, hc, tid);
    CP_COMMIT();

    if (tid < 64) rowsum[tid] = 0.0f;

    const int g8 = lane >> 3, r8 = lane & 7;
    const int wq = wid >> 1;
    const int wk = wid & 1;
    const int er = lane >> 2, ec2 = (lane & 3) * 2;

    const uint32_t aoA = (uint32_t)((wq * 16 + (g8 & 1) * 8 + r8) * AQS + (g8 >> 1) * 16);
    const uint32_t boB = (uint32_t)((wk * 32 + (g8 >> 1) * 8 + r8) * AQS + (g8 & 1) * 16);
    const uint32_t aoP = (uint32_t)((wq * 16 + (g8 & 1) * 8 + r8) * APS + (g8 >> 1) * 16);

    float acc2[16][4];
#pragma unroll
    for (int ni = 0; ni < 16; ni++)
#pragma unroll
        for (int j = 0; j < 4; j++) acc2[ni][j] = 0.0f;

    for (int ch = 0; ch < 9; ch++) {
        CP_WAIT(1);           // K(ch) (+Q on ch=0) complete
        __syncthreads();

        // ---- scores S[16q x 32keys] per warp ----
        float s[4][4];
#pragma unroll
        for (int ni = 0; ni < 4; ni++)
#pragma unroll
            for (int j = 0; j < 4; j++) s[ni][j] = 0.0f;

#pragma unroll 4
        for (int kk = 0; kk < 16; kk++) {
            uint32_t ka = kk * 32;
            uint32_t ahf[4];
            ldm_x4(ahf, sb + AT_Q + aoA + ka);
            uint32_t bhf[2][4];
#pragma unroll
            for (int nb = 0; nb < 2; nb++) {
                uint32_t o = boB + nb * 16 * AQS + ka;
                ldm_x4(bhf[nb], sb + AT_K + o);
            }
#pragma unroll
            for (int ni = 0; ni < 4; ni++) {
                const uint32_t* B2 = &bhf[ni >> 1][(ni & 1) * 2];
                mma16816(s[ni], ahf, B2);
            }
        }

        // ---- exp, row sums, P -> smem (fp16) ----
        float rs0 = 0.0f, rs1 = 0.0f;
#pragma unroll
        for (int ni = 0; ni < 4; ni++) {
            float p0 = __expf(s[ni][0] * 0.0625f);
            float p1 = __expf(s[ni][1] * 0.0625f);
            float p2 = __expf(s[ni][2] * 0.0625f);
            float p3 = __expf(s[ni][3] * 0.0625f);
            rs0 += p0 + p1;
            rs1 += p2 + p3;
            uint32_t hv0, hv1;
            { __half2 t2 = __halves2half2(__float2half_rn(p0), __float2half_rn(p1)); hv0 = *(uint32_t*)&t2; }
            { __half2 t2 = __halves2half2(__float2half_rn(p2), __float2half_rn(p3)); hv1 = *(uint32_t*)&t2; }
            int key = wk * 32 + ni * 8 + ec2;
            uint32_t po0 = (uint32_t)((wq * 16 + er) * APS + key * 2);
            uint32_t po1 = (uint32_t)((wq * 16 + er + 8) * APS + key * 2);
            *(uint32_t*)(smem + AT_PH + po0) = hv0;
            *(uint32_t*)(smem + AT_PH + po1) = hv1;
        }
        rs0 += __shfl_xor_sync(0xffffffffu, rs0, 1);
        rs0 += __shfl_xor_sync(0xffffffffu, rs0, 2);
        rs1 += __shfl_xor_sync(0xffffffffu, rs1, 1);
        rs1 += __shfl_xor_sync(0xffffffffu, rs1, 2);
        if ((lane & 3) == 0) {
            atomicAdd(&rowsum[wq * 16 + er], rs0);
            atomicAdd(&rowsum[wq * 16 + er + 8], rs1);
        }
        __syncthreads();      // P visible; K consumed by all warps

        // prefetch K(ch+1) over PV compute
        if (ch + 1 < 9) {
            at_load_k(sb, kh, b, ch + 1, hc, tid);
            CP_COMMIT();
            CP_WAIT(1);       // V(ch) complete (K(ch+1) may be in flight)
        } else {
            CP_WAIT(0);       // V(ch) complete
        }
        __syncthreads();      // V visible

        // ---- PV: X[16q x 128d] per warp over 64 keys ----
#pragma unroll
        for (int kk = 0; kk < 4; kk++) {
            uint32_t pa = kk * 32;
            uint32_t phf[4];
            ldm_x4(phf, sb + AT_PH + aoP + pa);
#pragma unroll
            for (int nb = 0; nb < 8; nb++) {
                int krow = kk * 16 + (g8 & 1) * 8 + r8;
                int dcol = wk * 128 + nb * 16 + (g8 >> 1) * 8;
                uint32_t vo = (uint32_t)(krow * AQS + dcol * 2);
                uint32_t bvh[4];
                ldm_x4t(bvh, sb + AT_V + vo);
                mma16816(acc2[2 * nb],     phf, &bvh[0]);
                mma16816(acc2[2 * nb + 1], phf, &bvh[2]);
            }
        }
        __syncthreads();      // V consumed by all warps

        // prefetch V(ch+1) over next QK compute
        if (ch + 1 < 9) {
            at_load_v(sb, vh, b, ch + 1, hc, tid);
            CP_COMMIT();
        }
    }

    // ---- normalize + write xh ----
    float inv0 = 1.0f / rowsum[wq * 16 + er];
    float inv1 = 1.0f / rowsum[wq * 16 + er + 8];
    size_t grow0 = ((size_t)(b * LT + q0 + wq * 16 + er)) * HID + hc;
    size_t grow1 = grow0 + (size_t)8 * HID;
#pragma unroll
    for (int ni = 0; ni < 16; ni++) {
        int col = wk * 128 + ni * 8 + ec2;
        float v0 = acc2[ni][0] * inv0, v1 = acc2[ni][1] * inv0;
        float v2 = acc2[ni][2] * inv1, v3 = acc2[ni][3] * inv1;
        uint32_t hv0, hv1;
        { __half2 t2 = __halves2half2(__float2half_rn(v0), __float2half_rn(v1)); hv0 = *(uint32_t*)&t2; }
        { __half2 t2 = __halves2half2(__float2half_rn(v2), __float2half_rn(v3)); hv1 = *(uint32_t*)&t2; }
        *(uint32_t*)(xh + grow0 + col) = hv0;
        *(uint32_t*)(xh + grow1 + col) = hv1;
    }
}

// ---------------------------------------------------------------------------
// Residual + LayerNorm:  out = LN(O + Y) * gamma + beta   (Y includes b2)
// 4 rows/block, 256 threads; thread owns cols tid, tid+256, tid+512.
// ---------------------------------------------------------------------------
__global__ __launch_bounds__(256) void ln_kernel(
    const float* __restrict__ O, const float* __restrict__ Y,
    const float* __restrict__ gamma, const float* __restrict__ beta,
    float* __restrict__ out)
{
    __shared__ float reds[4][8], redq[4][8];
    __shared__ float s_mu[4], s_rs[4];

    const int tid = threadIdx.x;
    const size_t row0 = (size_t)blockIdx.x * 4;

    float yv[4][3];
#pragma unroll
    for (int r = 0; r < 4; r++) {
#pragma unroll
        for (int c = 0; c < 3; c++) {
            size_t idx = (row0 + r) * TEXTD + tid + c * 256;
            yv[r][c] = O[idx] + Y[idx];
        }
    }

    const int lane = tid & 31, wd = tid >> 5;
#pragma unroll
    for (int r = 0; r < 4; r++) {
        float s = yv[r][0] + yv[r][1] + yv[r][2];
        float q = yv[r][0] * yv[r][0] + yv[r][1] * yv[r][1] + yv[r][2] * yv[r][2];
#pragma unroll
        for (int o = 16; o; o >>= 1) {
            s += __shfl_xor_sync(0xffffffffu, s, o);
            q += __shfl_xor_sync(0xffffffffu, q, o);
        }
        if (lane == 0) { reds[r][wd] = s; redq[r][wd] = q; }
    }
    __syncthreads();
    if (tid < 4) {
        float s = 0.0f, q = 0.0f;
#pragma unroll
        for (int w = 0; w < 8; w++) { s += reds[tid][w]; q += redq[tid][w]; }
        float m = s * (1.0f / TEXTD);
        float v = q * (1.0f / TEXTD) - m * m;
        s_mu[tid] = m;
        s_rs[tid] = rsqrtf(v + 1e-5f);
    }
    __syncthreads();

#pragma unroll
    for (int r = 0; r < 4; r++) {
        float m = s_mu[r], rs = s_rs[r];
#pragma unroll
        for (int c = 0; c < 3; c++) {
            int n = tid + c * 256;
            out[(row0 + r) * TEXTD + n] = (yv[r][c] - m) * rs * gamma[n] + beta[n];
        }
    }
}

// ---------------------------------------------------------------------------
// Launcher
// ---------------------------------------------------------------------------
extern "C" void kernel_launch(void* const* d_in, const int* in_sizes, int n_in,
                              void* d_out, int out_size)
{
    const float* text  = (const float*)d_in[0];
    const float* image = (const float*)d_in[1];
    const float* wq = (const float*)d_in[2];
    const float* bq = (const float*)d_in[3];
    const float* wk = (const float*)d_in[4];
    const float* bk = (const float*)d_in[5];
    const float* wv = (const float*)d_in[6];
    const float* bv = (const float*)d_in[7];
    const float* wr = (const float*)d_in[8];
    const float* br = (const float*)d_in[9];
    const float* w1 = (const float*)d_in[10];
    const float* b1 = (const float*)d_in[11];
    const float* w2 = (const float*)d_in[12];
    const float* b2 = (const float*)d_in[13];
    const float* gamma = (const float*)d_in[14];
    const float* beta  = (const float*)d_in[15];
    float* out = (float*)d_out;

    float *Op, *Yp;
    cudaGetSymbolAddress((void**)&Op, g_O);
    cudaGetSymbolAddress((void**)&Yp, g_Y);

    __half *th, *ih, *qh, *kh, *vh, *xh, *oh, *hh;
    __half *wqh, *wkh, *wvh, *wrh, *w1h, *w2h;
    cudaGetSymbolAddress((void**)&th, g_th);
    cudaGetSymbolAddress((void**)&ih, g_ih);
    cudaGetSymbolAddress((void**)&qh, g_qh);
    cudaGetSymbolAddress((void**)&kh, g_kh);
    cudaGetSymbolAddress((void**)&vh, g_vh);
    cudaGetSymbolAddress((void**)&xh, g_xh);
    cudaGetSymbolAddress((void**)&oh, g_oh);
    cudaGetSymbolAddress((void**)&hh, g_hh);
    cudaGetSymbolAddress((void**)&wqh, g_wqh);
    cudaGetSymbolAddress((void**)&wkh, g_wkh);
    cudaGetSymbolAddress((void**)&wvh, g_wvh);
    cudaGetSymbolAddress((void**)&wrh, g_wrh);
    cudaGetSymbolAddress((void**)&w1h, g_w1h);
    cudaGetSymbolAddress((void**)&w2h, g_w2h);

    cudaFuncSetAttribute(gemm_fp16, cudaFuncAttributeMaxDynamicSharedMemorySize,
                         GSMEM);
    cudaFuncSetAttribute(attn_hmma, cudaFuncAttributeMaxDynamicSharedMemorySize,
                         AT_SMEM);

    // --- conversions ---
    {
        int n4 = MQ * TEXTD / 4;
        cvt_h<<<(n4 + 255) / 256, 256>>>((const float4*)text, (__half2*)th, n4);
    }
    {
        int n4 = MK * IMGD / 4;
        cvt_h<<<(n4 + 255) / 256, 256>>>((const float4*)image, (__half2*)ih, n4);
    }
    cvt_trans_h<<<dim3(HID / 32, TEXTD / 32), dim3(32, 8)>>>(wq, wqh, TEXTD, HID);
    cvt_trans_h<<<dim3(HID / 32, IMGD / 32),  dim3(32, 8)>>>(wk, wkh, IMGD, HID);
    cvt_trans_h<<<dim3(HID / 32, IMGD / 32),  dim3(32, 8)>>>(wv, wvh, IMGD, HID);
    cvt_trans_h<<<dim3(TEXTD / 32, HID / 32), dim3(32, 8)>>>(wr, wrh, HID, TEXTD);
    cvt_trans_h<<<dim3(FFD / 32, TEXTD / 32), dim3(32, 8)>>>(w1, w1h, TEXTD, FFD);
    cvt_trans_h<<<dim3(TEXTD / 32, FFD / 32), dim3(32, 8)>>>(w2, w2h, FFD, TEXTD);

    // --- projection GEMMs -> fp16 ---
    gemm_fp16<<<dim3(HID / 128, MQ / 128), 256, GSMEM>>>(
        th, wqh, bq, nullptr, qh, MQ, HID, TEXTD, 1);
    gemm_fp16<<<dim3(HID / 128, MK / 128), 256, GSMEM>>>(
        ih, wkh, bk, nullptr, kh, MK, HID, IMGD, 1);
    gemm_fp16<<<dim3(HID / 128, MK / 128), 256, GSMEM>>>(
        ih, wvh, bv, nullptr, vh, MK, HID, IMGD, 1);

    // --- HMMA attention -> xh ---
    attn_hmma<<<dim3(LT / 64, HEADS, BATCH), 256, AT_SMEM>>>(qh, kh, vh, xh);

    // --- out projection -> fp32 O + fp16 Oh ---
    gemm_fp16<<<dim3(TEXTD / 128, MQ / 128), 256, GSMEM>>>(
        xh, wrh, br, Op, oh, MQ, TEXTD, HID, 2);

    // --- FF1: H = relu(Oh @ w1^T + b1) -> fp16 ---
    gemm_fp16<<<dim3(FFD / 128, MQ / 128), 256, GSMEM>>>(
        oh, w1h, b1, nullptr, hh, MQ, FFD, TEXTD, 3);

    // --- FF2: Y = H @ w2^T + b2 -> fp32 ---
    gemm_fp16<<<dim3(TEXTD / 128, MQ / 128), 256, GSMEM>>>(
        hh, w2h, b2, Yp, nullptr, MQ, TEXTD, FFD, 0);

    // --- residual + LayerNorm ---
    ln_kernel<<<MQ / 4, 256>>>(Op, Yp, gamma, beta, out);
}